// round 11
// baseline (speedup 1.0000x reference)
#include <cuda_runtime.h>
#include <math.h>
#include <stdint.h>

#define NPIX 3136   // 56*56 = 49 * 64 (exact M tiling)
#define CCH  256
#define HID  1024

// ---------------- scratch (allocation-free: __device__ globals) ----------------
__device__ float g_t1 [NPIX*CCH];
__device__ float g_qkv[NPIX*768];
__device__ float g_ao [NPIX*CCH];
__device__ float g_pr [NPIX*CCH];
__device__ float g_x1 [NPIX*CCH];
__device__ float g_t2 [NPIX*CCH];
__device__ float g_h  [NPIX*HID];

__device__ __forceinline__ uint32_t f2tf32(float f) {
    uint32_t r; asm("cvt.rna.tf32.f32 %0, %1;" : "=r"(r) : "f"(f)); return r;
}
__device__ __forceinline__ void cpasync16(uint32_t sa, const void* g) {
    asm volatile("cp.async.ca.shared.global [%0], [%1], 16;" :: "r"(sa), "l"(g) : "memory");
}
#define CP_COMMIT() asm volatile("cp.async.commit_group;" ::: "memory")
#define CP_WAIT1()  asm volatile("cp.async.wait_group 1;" ::: "memory")
#define CP_WAIT0()  asm volatile("cp.async.wait_group 0;" ::: "memory")

// ---------------- tf32 mma.sync GEMM with cp.async staging ----------------
// C[m,n] = act( sum_k A[m,k]*B[n,k] + bias[n] ). Tile 64x64, 4 warps (2x2), warp 32x32.
// K chunks of 32; raw fp32 staged via cp.async; tf32 cvt at fragment load.
// smem: As[2][64][36] | Bs[2][64][36] = 36864 B. ACT: 0 none, 1 GELU,
// 2 = fc2 fused epilogue: out[col*NPIX+row] = v + g_x1[row*CCH+col].
#define GEMM_SMEM 36864
template<int ACT>
__global__ void __launch_bounds__(128, 6) gemm_mma(const float* __restrict__ A,
                                                   const float* __restrict__ B,
                                                   const float* __restrict__ bias,
                                                   float* __restrict__ C, int N, int K)
{
    extern __shared__ float sm[];
    const int tid = threadIdx.x;
    const int wid = tid >> 5, lane = tid & 31;
    const int grp = lane >> 2, qid = lane & 3;
    const int wm = wid & 1, wn = wid >> 1;
    const int bm = blockIdx.y * 64, bn = blockIdx.x * 64;

    const int cr = tid >> 3, cc4 = (tid & 7) * 4;
    // 128 threads: each copies 4 rows (stride 16) x 16B for both A and B.

    float acc[2][4][4];
    #pragma unroll
    for (int mt = 0; mt < 2; mt++)
        #pragma unroll
        for (int nt = 0; nt < 4; nt++)
            #pragma unroll
            for (int r = 0; r < 4; r++) acc[mt][nt][r] = 0.f;

    const int S = K >> 5;
    const uint32_t sA = (uint32_t)__cvta_generic_to_shared(sm);
    const uint32_t sB = sA + 4608u * 4u;

    auto copyAB = [&](int b, int kc) {
        const uint32_t offA = sA + (uint32_t)b * 2304u * 4u;
        const uint32_t offB = sB + (uint32_t)b * 2304u * 4u;
        #pragma unroll
        for (int it = 0; it < 4; it++) {
            const int r = cr + it*16;
            const uint32_t so = (uint32_t)(r*36 + cc4) * 4u;
            cpasync16(offA + so, &A[(size_t)(bm + r)*K + kc + cc4]);
            cpasync16(offB + so, &B[(size_t)(bn + r)*K + kc + cc4]);
        }
    };

    copyAB(0, 0);
    CP_COMMIT();

    for (int i = 0; i < S; i++) {
        if (i + 1 < S) {
            copyAB((i + 1) & 1, (i + 1) * 32);
            CP_COMMIT();
            CP_WAIT1();
        } else {
            CP_WAIT0();
        }
        __syncthreads();

        const float* As = sm + (i & 1)*2304;
        const float* Bs = sm + 4608 + (i & 1)*2304;
        #pragma unroll
        for (int kt = 0; kt < 4; kt++) {
            uint32_t a[2][4], b[4][2];
            #pragma unroll
            for (int mt = 0; mt < 2; mt++) {
                const int r0 = wm*32 + mt*16 + grp;
                const int c0 = kt*8 + qid;
                a[mt][0] = f2tf32(As[ r0    *36 + c0    ]);
                a[mt][1] = f2tf32(As[(r0+8) *36 + c0    ]);
                a[mt][2] = f2tf32(As[ r0    *36 + c0 + 4]);
                a[mt][3] = f2tf32(As[(r0+8) *36 + c0 + 4]);
            }
            #pragma unroll
            for (int nt = 0; nt < 4; nt++) {
                const int n0 = wn*32 + nt*8 + grp;
                const int k0 = kt*8 + qid;
                b[nt][0] = f2tf32(Bs[n0*36 + k0    ]);
                b[nt][1] = f2tf32(Bs[n0*36 + k0 + 4]);
            }
            #pragma unroll
            for (int mt = 0; mt < 2; mt++)
                #pragma unroll
                for (int nt = 0; nt < 4; nt++)
                    asm volatile(
                        "mma.sync.aligned.m16n8k8.row.col.f32.tf32.tf32.f32 "
                        "{%0,%1,%2,%3}, {%4,%5,%6,%7}, {%8,%9}, {%0,%1,%2,%3};"
                        : "+f"(acc[mt][nt][0]), "+f"(acc[mt][nt][1]),
                          "+f"(acc[mt][nt][2]), "+f"(acc[mt][nt][3])
                        : "r"(a[mt][0]), "r"(a[mt][1]), "r"(a[mt][2]), "r"(a[mt][3]),
                          "r"(b[nt][0]), "r"(b[nt][1]));
        }
        __syncthreads();
    }

    // epilogue
    #pragma unroll
    for (int mt = 0; mt < 2; mt++) {
        #pragma unroll
        for (int nt = 0; nt < 4; nt++) {
            const int row0 = bm + wm*32 + mt*16 + grp;
            const int col  = bn + wn*32 + nt*8 + qid*2;
            const float b0 = bias[col], b1 = bias[col+1];
            float v0 = acc[mt][nt][0] + b0;
            float v1 = acc[mt][nt][1] + b1;
            float v2 = acc[mt][nt][2] + b0;
            float v3 = acc[mt][nt][3] + b1;
            if (ACT == 1) {
                v0 = 0.5f*v0*(1.f + erff(v0*0.70710678118654752f));
                v1 = 0.5f*v1*(1.f + erff(v1*0.70710678118654752f));
                v2 = 0.5f*v2*(1.f + erff(v2*0.70710678118654752f));
                v3 = 0.5f*v3*(1.f + erff(v3*0.70710678118654752f));
            }
            if (ACT == 2) {
                // fused: out[c, n] = v + x1[n, c]  (transpose store to d_out)
                C[(size_t)(col  )*NPIX + row0    ] = v0 + g_x1[(size_t)(row0  )*CCH + col  ];
                C[(size_t)(col+1)*NPIX + row0    ] = v1 + g_x1[(size_t)(row0  )*CCH + col+1];
                C[(size_t)(col  )*NPIX + row0 + 8] = v2 + g_x1[(size_t)(row0+8)*CCH + col  ];
                C[(size_t)(col+1)*NPIX + row0 + 8] = v3 + g_x1[(size_t)(row0+8)*CCH + col+1];
            } else {
                *(float2*)&C[(size_t)row0*N + col]     = make_float2(v0, v1);
                *(float2*)&C[(size_t)(row0+8)*N + col] = make_float2(v2, v3);
            }
        }
    }
}

// ---------------- channel LayerNorm (+optional residual add) ----------------
template <bool ADD>
__global__ void ln_kernel(const float* __restrict__ x,
                          const float* __restrict__ w, const float* __restrict__ b,
                          float* __restrict__ t)
{
    __shared__ float s[CCH][33];
    __shared__ float rsum[8][32], rsum2[8][32];
    __shared__ float mu_s[32], rs_s[32];
    const int tid  = threadIdx.x;
    const int lane = tid & 31, wp = tid >> 5;
    const int p0   = blockIdx.x * 32;

    if (ADD) {
        const int cl = tid & 31, pl8 = tid >> 5;
        #pragma unroll
        for (int pp = 0; pp < 4; pp++) {
            const int pl = pp*8 + pl8;
            #pragma unroll
            for (int cc = 0; cc < 8; cc++) {
                const int c = cc*32 + cl;
                s[c][pl] = g_pr[(p0+pl)*CCH + c];
            }
        }
        __syncthreads();
    }
    float sum = 0.f, sum2 = 0.f;
    #pragma unroll
    for (int k = 0; k < 32; k++) {
        const int c = wp*32 + k;
        float v = x[c*NPIX + p0 + lane];
        if (ADD) v += s[c][lane];
        s[c][lane] = v;
        sum += v; sum2 += v*v;
    }
    rsum[wp][lane] = sum; rsum2[wp][lane] = sum2;
    __syncthreads();
    if (tid < 32) {
        float a = 0.f, a2 = 0.f;
        #pragma unroll
        for (int k = 0; k < 8; k++) { a += rsum[k][tid]; a2 += rsum2[k][tid]; }
        const float mu  = a * (1.f/CCH);
        const float var = a2 * (1.f/CCH) - mu*mu;
        mu_s[tid] = mu; rs_s[tid] = rsqrtf(var + 1e-5f);
    }
    __syncthreads();
    {
        const int cl = tid & 31, pl8 = tid >> 5;
        #pragma unroll
        for (int pp = 0; pp < 4; pp++) {
            const int pl = pp*8 + pl8;
            const float mu = mu_s[pl], rs = rs_s[pl];
            #pragma unroll
            for (int cc = 0; cc < 8; cc++) {
                const int c = cc*32 + cl;
                const float y = s[c][pl];
                if (ADD) g_x1[(p0+pl)*CCH + c] = y;
                t[(p0+pl)*CCH + c] = (y - mu)*rs*w[c] + b[c];
            }
        }
    }
}

// ---------------- local window attention (tiled smem, known-good) ----------------
__global__ void attn_kernel()
{
    __shared__ float Ks[196][36];
    __shared__ float Vs[196][36];
    __shared__ float Ps[64][56];
    const int tid = threadIdx.x;
    const int h  = blockIdx.z;
    const int ti = blockIdx.y, tj = blockIdx.x;
    const int gi0 = ti*8 - 3, gj0 = tj*8 - 3;

    for (int idx = tid; idx < 196*32; idx += 256) {
        const int pix = idx >> 5, d = idx & 31;
        const int pi = pix / 14, pj = pix - pi*14;
        const int ai = gi0 + pi, aj = gj0 + pj;
        float kv = 0.f, vv = 0.f;
        if (ai >= 0 && ai < 56 && aj >= 0 && aj < 56) {
            const int m = ai*56 + aj;
            kv = g_qkv[m*768 + 256 + h*32 + d];
            vv = g_qkv[m*768 + 512 + h*32 + d];
        }
        Ks[pix][d] = kv;
        Vs[pix][d] = vv;
    }
    __syncthreads();

    const int q  = tid >> 2, qu = tid & 3;
    const int qi = q >> 3,  qj = q & 7;
    const int gqi = ti*8 + qi, gqj = tj*8 + qj;
    const int n = gqi*56 + gqj;

    float qv[32];
    {
        const float4* qp = (const float4*)&g_qkv[n*768 + h*32];
        #pragma unroll
        for (int k = 0; k < 8; k++) {
            const float4 v = qp[k];
            qv[4*k+0] = v.x; qv[4*k+1] = v.y; qv[4*k+2] = v.z; qv[4*k+3] = v.w;
        }
    }

    float sc[13];
    #pragma unroll
    for (int j = 0; j < 13; j++) sc[j] = -3.0e38f;
    #pragma unroll
    for (int j = 0; j < 13; j++) {
        const int s = qu + 4*j;
        if (s < 49) {
            const int dy = s / 7 - 3, dx = s - (s/7)*7 - 3;
            const int ai = gqi + dy, aj = gqj + dx;
            if (ai >= 0 && ai < 56 && aj >= 0 && aj < 56) {
                const int nb = (qi + dy + 3)*14 + (qj + dx + 3);
                const float4* kp = (const float4*)&Ks[nb][0];
                float acc = 0.f;
                #pragma unroll
                for (int k = 0; k < 8; k++) {
                    const float4 kv = kp[k];
                    acc += qv[4*k+0]*kv.x + qv[4*k+1]*kv.y
                         + qv[4*k+2]*kv.z + qv[4*k+3]*kv.w;
                }
                sc[j] = acc * 0.17677669529663687f;
            }
        }
    }

    const unsigned FULL = 0xffffffffu;
    float mx = sc[0];
    #pragma unroll
    for (int j = 1; j < 13; j++) mx = fmaxf(mx, sc[j]);
    mx = fmaxf(mx, __shfl_xor_sync(FULL, mx, 1));
    mx = fmaxf(mx, __shfl_xor_sync(FULL, mx, 2));
    float lsum = 0.f;
    float pe[13];
    #pragma unroll
    for (int j = 0; j < 13; j++) { pe[j] = __expf(sc[j] - mx); lsum += pe[j]; }
    lsum += __shfl_xor_sync(FULL, lsum, 1);
    lsum += __shfl_xor_sync(FULL, lsum, 2);
    const float inv = 1.f / lsum;
    #pragma unroll
    for (int j = 0; j < 13; j++) {
        const int s = qu + 4*j;
        if (s < 49) Ps[q][s] = pe[j] * inv;
    }
    __syncthreads();

    const int d0 = qu*8;
    float acc[8] = {};
    #pragma unroll
    for (int dy = -3; dy <= 3; dy++) {
        const int rowbase = (qi + dy + 3)*14 + (qj + 3);
        const int sbase = (dy+3)*7;
        #pragma unroll
        for (int dx = -3; dx <= 3; dx++) {
            const float p = Ps[q][sbase + dx + 3];
            const float4* vp = (const float4*)&Vs[rowbase + dx][d0];
            const float4 v0 = vp[0], v1 = vp[1];
            acc[0] += p*v0.x; acc[1] += p*v0.y; acc[2] += p*v0.z; acc[3] += p*v0.w;
            acc[4] += p*v1.x; acc[5] += p*v1.y; acc[6] += p*v1.z; acc[7] += p*v1.w;
        }
    }
    float4* op = (float4*)&g_ao[n*CCH + h*32 + d0];
    op[0] = make_float4(acc[0], acc[1], acc[2], acc[3]);
    op[1] = make_float4(acc[4], acc[5], acc[6], acc[7]);
}

extern "C" void kernel_launch(void* const* d_in, const int* in_sizes, int n_in,
                              void* d_out, int out_size)
{
    const float* x       = (const float*)d_in[0];
    const float* norm1_w = (const float*)d_in[1];
    const float* norm1_b = (const float*)d_in[2];
    const float* qkv_w   = (const float*)d_in[3];
    const float* qkv_b   = (const float*)d_in[4];
    const float* proj_w  = (const float*)d_in[5];
    const float* proj_b  = (const float*)d_in[6];
    const float* norm2_w = (const float*)d_in[7];
    const float* norm2_b = (const float*)d_in[8];
    const float* fc1_w   = (const float*)d_in[9];
    const float* fc1_b   = (const float*)d_in[10];
    const float* fc2_w   = (const float*)d_in[11];
    const float* fc2_b   = (const float*)d_in[12];
    float* out = (float*)d_out;

    static float *t1 = nullptr, *qkv = nullptr, *t2 = nullptr, *hbuf = nullptr,
                 *ao = nullptr, *pr = nullptr;
    if (!t1) {
        cudaGetSymbolAddress((void**)&t1,   g_t1);
        cudaGetSymbolAddress((void**)&qkv,  g_qkv);
        cudaGetSymbolAddress((void**)&ao,   g_ao);
        cudaGetSymbolAddress((void**)&t2,   g_t2);
        cudaGetSymbolAddress((void**)&hbuf, g_h);
        cudaGetSymbolAddress((void**)&pr,   g_pr);
        cudaFuncSetAttribute(gemm_mma<0>, cudaFuncAttributeMaxDynamicSharedMemorySize, GEMM_SMEM);
        cudaFuncSetAttribute(gemm_mma<1>, cudaFuncAttributeMaxDynamicSharedMemorySize, GEMM_SMEM);
        cudaFuncSetAttribute(gemm_mma<2>, cudaFuncAttributeMaxDynamicSharedMemorySize, GEMM_SMEM);
    }

    // 1. LN1
    ln_kernel<false><<<NPIX/32, 256>>>(x, norm1_w, norm1_b, t1);
    // 2. QKV: [3136,768]
    gemm_mma<0><<<dim3(768/64, NPIX/64), 128, GEMM_SMEM>>>(t1, qkv_w, qkv_b, qkv, 768, CCH);
    // 3. local attention
    attn_kernel<<<dim3(7, 7, 8), 256>>>();
    // 4. proj
    gemm_mma<0><<<dim3(CCH/64, NPIX/64), 128, GEMM_SMEM>>>(ao, proj_w, proj_b, pr, CCH, CCH);
    // 5. x1 = x + pr ; t2 = LN(x1)
    ln_kernel<true><<<NPIX/32, 256>>>(x, norm2_w, norm2_b, t2);
    // 6. fc1 + GELU
    gemm_mma<1><<<dim3(HID/64, NPIX/64), 128, GEMM_SMEM>>>(t2, fc1_w, fc1_b, hbuf, HID, CCH);
    // 7. fc2 fused with residual-add + transpose store to d_out
    gemm_mma<2><<<dim3(CCH/64, NPIX/64), 128, GEMM_SMEM>>>(hbuf, fc2_w, fc2_b, out, CCH, HID);
}